// round 16
// baseline (speedup 1.0000x reference)
#include <cuda_runtime.h>
#include <cuda_bf16.h>
#include <cstdint>

// ---------------------------------------------------------------------------
// EncoderBiLSTMMaxPool — sequential schedule (R8 structure), new LSTM core:
//   embed_split -> a2 [hi|lo] bf16
//   w_split     -> w2 [hi|hi|lo] with OUTPUT-COLUMN PERMUTATION
//                  n' = dir*1024 + unit*4 + gate  (+ permuted bias array)
//   gemm0 -> gx0 (permuted cols), lstm layer0 (writes a2 split),
//   gemm1 -> gx1, lstm layer1 (writes y1), maxpool.
// LSTM core: 128 thr/CTA, 1 full gate row per thread (256-wide dot in regs),
//   shfl-based gate combine, NO __syncthreads in the step loop.
// GEMM numerics: 3-term bf16 hi/lo split => rel_err ~5e-6 (proven R8+).
// ---------------------------------------------------------------------------

#define Bn   128
#define Sn   128
#define Hn   512
#define NROW 16384
#define GXN  2048
#define KA   1024
#define KW   1536

typedef unsigned long long ull;

__device__ __align__(16) float          g_x0[NROW * GXN];
__device__ __align__(16) float          g_x1[NROW * GXN];
__device__ __align__(16) __nv_bfloat16  g_a2[(long)NROW * KA];
__device__ __align__(16) __nv_bfloat16  g_w2[2L * GXN * KW];
__device__ float g_bias[2 * GXN];        // permuted bih+bhh per layer

// ---------------------------------------------------------------------------
// helpers
// ---------------------------------------------------------------------------
__device__ __forceinline__ unsigned smem_u32(const void* p) {
    return (unsigned)__cvta_generic_to_shared(p);
}
__device__ __forceinline__ unsigned mapa_cluster(unsigned addr, unsigned rank) {
    unsigned r;
    asm volatile("mapa.shared::cluster.u32 %0, %1, %2;" : "=r"(r) : "r"(addr), "r"(rank));
    return r;
}
__device__ __forceinline__ void cluster_sync_() {
    asm volatile("barrier.cluster.arrive.aligned;" ::: "memory");
    asm volatile("barrier.cluster.wait.aligned;" ::: "memory");
}
__device__ __forceinline__ void mbar_init(unsigned bar, unsigned cnt) {
    asm volatile("mbarrier.init.shared.b64 [%0], %1;" :: "r"(bar), "r"(cnt) : "memory");
}
__device__ __forceinline__ void mbar_arm(unsigned bar, unsigned tx) {
    asm volatile("mbarrier.arrive.expect_tx.shared::cta.b64 _, [%0], %1;"
                 :: "r"(bar), "r"(tx) : "memory");
}
__device__ __forceinline__ void mbar_wait(unsigned bar, unsigned parity) {
    asm volatile(
        "{\n\t.reg .pred P;\n"
        "LW%=:\n\t"
        "mbarrier.try_wait.parity.acquire.cta.shared::cta.b64 P, [%0], %1, 0x989680;\n\t"
        "@!P bra LW%=;\n\t}"
        :: "r"(bar), "r"(parity) : "memory");
}
__device__ __forceinline__ void st_async_f32(unsigned dst, float v, unsigned bar) {
    asm volatile("st.async.shared::cluster.mbarrier::complete_tx::bytes.b32 [%0], %1, [%2];"
                 :: "r"(dst), "r"(__float_as_uint(v)), "r"(bar) : "memory");
}
__device__ __forceinline__ float tanh_fast(float x) {
    float r;
    asm("tanh.approx.f32 %0, %1;" : "=f"(r) : "f"(x));
    return r;
}
__device__ __forceinline__ float sigmoid_fast(float x) {
    return fmaf(0.5f, tanh_fast(0.5f * x), 0.5f);
}
__device__ __forceinline__ void fma2(ull& acc, ull a, ull b) {
    asm("fma.rn.f32x2 %0, %1, %2, %0;" : "+l"(acc) : "l"(a), "l"(b));
}
__device__ __forceinline__ float sum2(ull a) {
    unsigned lo, hi;
    asm("mov.b64 {%0,%1}, %2;" : "=r"(lo), "=r"(hi) : "l"(a));
    return __uint_as_float(lo) + __uint_as_float(hi);
}

// --- mma.sync / ldmatrix / cp.async ---
__device__ __forceinline__ void cp16(unsigned dst, const void* src) {
    asm volatile("cp.async.cg.shared.global [%0], [%1], 16;" :: "r"(dst), "l"(src));
}
__device__ __forceinline__ void cp_commit() {
    asm volatile("cp.async.commit_group;" ::: "memory");
}
__device__ __forceinline__ void cp_wait3() {
    asm volatile("cp.async.wait_group 3;" ::: "memory");
}
__device__ __forceinline__ void ldsm4(unsigned* r, unsigned addr) {
    asm volatile("ldmatrix.sync.aligned.m8n8.x4.shared.b16 {%0,%1,%2,%3}, [%4];"
                 : "=r"(r[0]), "=r"(r[1]), "=r"(r[2]), "=r"(r[3]) : "r"(addr));
}
__device__ __forceinline__ void mma16816(float* c, const unsigned* a,
                                         unsigned b0, unsigned b1) {
    asm volatile(
        "mma.sync.aligned.m16n8k16.row.col.f32.bf16.bf16.f32 "
        "{%0,%1,%2,%3}, {%4,%5,%6,%7}, {%8,%9}, {%0,%1,%2,%3};"
        : "+f"(c[0]), "+f"(c[1]), "+f"(c[2]), "+f"(c[3])
        : "r"(a[0]), "r"(a[1]), "r"(a[2]), "r"(a[3]), "r"(b0), "r"(b1));
}

__device__ __forceinline__ uint2 pack4bf16(float a, float b, float c, float d) {
    __nv_bfloat162 p0 = __floats2bfloat162_rn(a, b);
    __nv_bfloat162 p1 = __floats2bfloat162_rn(c, d);
    uint2 r;
    r.x = *(unsigned*)&p0;
    r.y = *(unsigned*)&p1;
    return r;
}
__device__ __forceinline__ void split4(const float* v, float* hi, float* lo) {
#pragma unroll
    for (int j = 0; j < 4; j++) {
        __nv_bfloat16 h = __float2bfloat16_rn(v[j]);
        hi[j] = __bfloat162float(h);
        lo[j] = v[j] - hi[j];
    }
}

// ---------------------------------------------------------------------------
// 1) embedding sum + split -> a2 rows [hi | lo]
// ---------------------------------------------------------------------------
__global__ void embed_split_kernel(const int* __restrict__ rt, const int* __restrict__ re,
                                   const int* __restrict__ rm,
                                   const float* __restrict__ Ert, const float* __restrict__ Ere,
                                   const float* __restrict__ Erm)
{
    int row = blockIdx.x;
    int t   = threadIdx.x;
    long irt = rt[row], ire = re[row], irm = rm[row];
    float4 va = ((const float4*)(Ert + irt * (long)Hn))[t];
    float4 vb = ((const float4*)(Ere + ire * (long)Hn))[t];
    float4 vc = ((const float4*)(Erm + irm * (long)Hn))[t];
    float v[4] = { va.x + vb.x + vc.x, va.y + vb.y + vc.y,
                   va.z + vb.z + vc.z, va.w + vb.w + vc.w };
    float hi[4], lo[4];
    split4(v, hi, lo);
    __nv_bfloat16* ro = g_a2 + (long)row * KA + 4 * t;
    *(uint2*)(ro)       = pack4bf16(hi[0], hi[1], hi[2], hi[3]);
    *(uint2*)(ro + 512) = pack4bf16(lo[0], lo[1], lo[2], lo[3]);
}

// split Wih -> w2 rows [hi | hi | lo], with output-row permutation:
//   output row n' hosts original W row  dir*1024 + gate*256 + unit,
//   where dir=n'>>10, unit=(n'&1023)>>2, gate=n'&3.
// Also emits permuted bias: g_bias[l*2048 + n'] = bih[orig] + bhh[orig].
__global__ void w_split_kernel(const float* __restrict__ Wih,
                               const float* __restrict__ bih,
                               const float* __restrict__ bhh)
{
    int np = blockIdx.x;       // permuted output row 0..2047
    int l  = blockIdx.y;
    int t  = threadIdx.x;
    int d    = np >> 10;
    int r    = np & 1023;
    int unit = r >> 2;
    int gate = r & 3;
    int orig = d * 1024 + gate * 256 + unit;

    float4 vv = *(const float4*)(Wih + ((long)l * 2048 + orig) * 512 + 4 * t);
    float v[4] = { vv.x, vv.y, vv.z, vv.w };
    float hi[4], lo[4];
    split4(v, hi, lo);
    __nv_bfloat16* ro = g_w2 + ((long)l * 2048 + np) * KW + 4 * t;
    uint2 ph = pack4bf16(hi[0], hi[1], hi[2], hi[3]);
    *(uint2*)(ro)        = ph;
    *(uint2*)(ro + 512)  = ph;
    *(uint2*)(ro + 1024) = pack4bf16(lo[0], lo[1], lo[2], lo[3]);

    if (t == 0)
        g_bias[l * 2048 + np] = bih[l * 2048 + orig] + bhh[l * 2048 + orig];
}

// ---------------------------------------------------------------------------
// 2) mma.sync bf16 GEMM over K=1536 (A k-map: k>=1024 re-reads hi block).
//    Block 128x128, warps 4x2, warp tile 32x64, BK=32, 5-stage cp.async.
//    bias: permuted array.
// ---------------------------------------------------------------------------
#define ROWB       80
#define A_BYTES    (128 * ROWB)
#define STAGE_B    (2 * A_BYTES)
#define NSTAGE     5
#define GEMM_SMEM  (NSTAGE * STAGE_B)     // 102400
#define NKT        (KW / 32)              // 48

__global__ __launch_bounds__(256, 2) void gemm_mma_kernel(
    const __nv_bfloat16* __restrict__ A2, const __nv_bfloat16* __restrict__ W2,
    const float* __restrict__ bias, float* __restrict__ C)
{
    extern __shared__ __align__(16) char dyn[];
    __shared__ float bias_s[128];

    const int tid  = threadIdx.x;
    const int wid  = tid >> 5;
    const int lane = tid & 31;
    const int wm   = wid & 3;
    const int wn   = wid >> 2;
    const int bm = blockIdx.y * 128;
    const int bn = blockIdx.x * 128;

    if (tid < 128) bias_s[tid] = bias[bn + tid];

    const unsigned sbase = smem_u32(dyn);
    const int g  = lane >> 3;
    const int rr = lane & 7;
    const unsigned a_lane = (unsigned)((wm * 32 + (g & 1) * 8 + rr) * ROWB + (g >> 1) * 16);
    const unsigned b_lane = (unsigned)((wn * 64 + (g >> 1) * 8 + rr) * ROWB + (g & 1) * 16);

    float acc[2][8][4];
#pragma unroll
    for (int i = 0; i < 2; i++)
#pragma unroll
        for (int j = 0; j < 8; j++)
#pragma unroll
            for (int q = 0; q < 4; q++) acc[i][j][q] = 0.f;

    auto issue_loads = [&](int kt) {
        unsigned stage = sbase + (unsigned)(kt % NSTAGE) * STAGE_B;
        long k0 = (long)kt * 32;
        long ak = (k0 < 1024) ? k0 : (k0 - 1024);
#pragma unroll
        for (int i = 0; i < 4; i++) {
            int c = tid + i * 256;
            if (c < 512) {
                int row = c >> 2, ch = c & 3;
                cp16(stage + row * ROWB + ch * 16,
                     A2 + (long)(bm + row) * KA + ak + ch * 8);
            } else {
                int c2 = c - 512;
                int row = c2 >> 2, ch = c2 & 3;
                cp16(stage + A_BYTES + row * ROWB + ch * 16,
                     W2 + (long)(bn + row) * KW + k0 + ch * 8);
            }
        }
    };

    issue_loads(0); cp_commit();
    issue_loads(1); cp_commit();
    issue_loads(2); cp_commit();
    issue_loads(3); cp_commit();

    for (int kt = 0; kt < NKT; kt++) {
        cp_wait3();
        __syncthreads();
        unsigned stage  = sbase + (unsigned)(kt % NSTAGE) * STAGE_B;
        unsigned stageB = stage + A_BYTES;
#pragma unroll
        for (int kk = 0; kk < 2; kk++) {
            unsigned afrag[2][4];
#pragma unroll
            for (int mi = 0; mi < 2; mi++)
                ldsm4(afrag[mi], stage + a_lane + mi * 16 * ROWB + kk * 32);
            unsigned bfrag[4][4];
#pragma unroll
            for (int p = 0; p < 4; p++)
                ldsm4(bfrag[p], stageB + b_lane + p * 16 * ROWB + kk * 32);
#pragma unroll
            for (int mi = 0; mi < 2; mi++)
#pragma unroll
                for (int p = 0; p < 4; p++) {
                    mma16816(acc[mi][2 * p],     afrag[mi], bfrag[p][0], bfrag[p][1]);
                    mma16816(acc[mi][2 * p + 1], afrag[mi], bfrag[p][2], bfrag[p][3]);
                }
        }
        __syncthreads();
        if (kt + 4 < NKT) issue_loads(kt + 4);
        cp_commit();
    }

    const int trow = lane >> 2;
    const int tcol = (lane & 3) * 2;
#pragma unroll
    for (int mi = 0; mi < 2; mi++) {
        int m0 = bm + wm * 32 + mi * 16 + trow;
#pragma unroll
        for (int nj = 0; nj < 8; nj++) {
            int cl = wn * 64 + nj * 8 + tcol;
            int n0 = bn + cl;
            float b0 = bias_s[cl], b1 = bias_s[cl + 1];
            *(float2*)(C + (long)m0 * GXN + n0) =
                make_float2(acc[mi][nj][0] + b0, acc[mi][nj][1] + b1);
            *(float2*)(C + (long)(m0 + 8) * GXN + n0) =
                make_float2(acc[mi][nj][2] + b0, acc[mi][nj][3] + b1);
        }
    }
}

// ---------------------------------------------------------------------------
// 3) LSTM recurrence, shfl-combine core. 8 clusters of 8 CTAs, 128 thr/CTA.
//    tid = ul*4 + gate; thread owns FULL gate row (256-wide dot in regs).
//    gx columns are permuted (dir*1024 + unit*4 + gate) -> xcol = dir*1024
//    + rank*128 + tid (coalesced). NO __syncthreads in the loop.
//    layer==0 writes a2 (split bf16), layer==1 writes y1 fp32.
// ---------------------------------------------------------------------------
__global__ void __cluster_dims__(8, 1, 1) __launch_bounds__(128, 1)
lstm_layer_kernel(const float* __restrict__ Whh, const float* __restrict__ gx,
                  float* __restrict__ y1, __nv_bfloat16* __restrict__ a2,
                  const float* __restrict__ h0, const float* __restrict__ c0,
                  int layer)
{
    __shared__ __align__(16) float h_buf[2][256];
    __shared__ __align__(8) ull mbar[2];

    unsigned rank;
    asm("mov.u32 %0, %%cluster_ctarank;" : "=r"(rank));
    const int cluster_id = blockIdx.x >> 3;
    const int group = cluster_id & 3;
    const int dir   = cluster_id >> 2;
    const int tid  = threadIdx.x;        // 0..127
    const int lane = tid & 31;
    const int ul   = tid >> 2;           // unit local 0..31
    const int gate = tid & 3;            // 0:i 1:f 2:g 3:o
    const int unit = (int)rank * 32 + ul;
    const int grow = gate * 256 + unit;  // original Whh row

    // full 256-wide weight row in registers (64 x f32x2 pairs = 128 regs)
    ulonglong2 w[32];
    ulonglong2 w2r[32];
    {
        const ulonglong2* wsrc = (const ulonglong2*)(Whh
            + ((long)(layer * 2 + dir) * 1024 + grow) * 256);
#pragma unroll
        for (int j = 0; j < 32; j++) w[j] = wsrc[j];
#pragma unroll
        for (int j = 0; j < 32; j++) w2r[j] = wsrc[32 + j];
    }

    const int sidx = (layer * 2 + dir) * 256;
    // init h_buf[0] (256 entries, 128 threads -> 2 each)
    h_buf[0][tid]       = (group == 0) ? h0[sidx + tid] : 0.f;
    h_buf[0][tid + 128] = (group == 0) ? h0[sidx + tid + 128] : 0.f;
    float creg = (group == 0) ? c0[sidx + unit] : 0.f;   // replicated x4 lanes

    unsigned mb0 = smem_u32(&mbar[0]);
    unsigned mb1 = smem_u32(&mbar[1]);
    if (tid == 0) {
        mbar_init(mb0, 1);
        mbar_init(mb1, 1);
        mbar_arm(mb1, 1024);   // consumed at q=1
        mbar_arm(mb0, 1024);   // consumed at q=2
    }
    __syncthreads();
    cluster_sync_();

    const int xcol = dir * 1024 + (int)rank * 128 + tid;   // permuted, coalesced
    const int ycol = dir * 256 + unit;
    const long mbase = (long)group * 32 * 128;
    unsigned ph0 = 0, ph1 = 0;

    auto midx = [&](int q) -> long {
        int t = q & 127;
        if (dir) t = 127 - t;
        return mbase + (q & ~127) + t;
    };

    const bool is_store = (gate == 0);
    const unsigned gbase = lane & 0x1C;    // lane of gate 0 in this unit group

    float xcur = __ldg(gx + midx(0) * GXN + xcol);

    for (int q = 0; q < 4096; q++) {
        const int p = q & 1;

        float xnext = 0.f;
        if (q + 1 < 4096)
            xnext = __ldg(gx + midx(q + 1) * GXN + xcol);

        if (q > 0) {
            if (p) { mbar_wait(mb1, ph1); ph1 ^= 1; }
            else   { mbar_wait(mb0, ph0); ph0 ^= 1; }
            if (tid == 1) mbar_arm(p ? mb1 : mb0, 1024);   // re-arm for q+2
        }

        // full 256-wide dot: 128 FFMA2 (broadcast LDS: lane-invariant addr)
        const ulonglong2* hb = (const ulonglong2*)h_buf[p];
        ull a0 = 0, a1 = 0, a2r = 0, a3 = 0;
#pragma unroll
        for (int j = 0; j < 32; j += 2) {
            ulonglong2 hv = hb[j];
            fma2(a0, hv.x, w[j].x);
            fma2(a1, hv.y, w[j].y);
            ulonglong2 hv2 = hb[j + 1];
            fma2(a2r, hv2.x, w[j + 1].x);
            fma2(a3, hv2.y, w[j + 1].y);
        }
#pragma unroll
        for (int j = 0; j < 32; j += 2) {
            ulonglong2 hv = hb[32 + j];
            fma2(a0, hv.x, w2r[j].x);
            fma2(a1, hv.y, w2r[j].y);
            ulonglong2 hv2 = hb[32 + j + 1];
            fma2(a2r, hv2.x, w2r[j + 1].x);
            fma2(a3, hv2.y, w2r[j + 1].y);
        }
        float s = (sum2(a0) + sum2(a1)) + (sum2(a2r) + sum2(a3)) + xcur;

        // per-lane activation, then gather the 4 gates of this unit
        float act = (gate == 2) ? tanh_fast(s) : sigmoid_fast(s);
        float ai = __shfl_sync(0xFFFFFFFFu, act, gbase + 0);
        float af = __shfl_sync(0xFFFFFFFFu, act, gbase + 1);
        float ag = __shfl_sync(0xFFFFFFFFu, act, gbase + 2);
        float ao = __shfl_sync(0xFFFFFFFFu, act, gbase + 3);
        creg = fmaf(af, creg, ai * ag);
        float h = ao * tanh_fast(creg);

        if (is_store) {
            const int pn = p ^ 1;
            unsigned ldst = smem_u32(&h_buf[pn][unit]);
            unsigned lbar = pn ? mb1 : mb0;
#pragma unroll
            for (unsigned r = 0; r < 8; r++)
                st_async_f32(mapa_cluster(ldst, r), h, mapa_cluster(lbar, r));

            const long m = midx(q);
            if (layer == 0) {
                __nv_bfloat16 hb16 = __float2bfloat16_rn(h);
                float hf = __bfloat162float(hb16);
                __nv_bfloat16 lb16 = __float2bfloat16_rn(h - hf);
                a2[m * KA + ycol]       = hb16;
                a2[m * KA + 512 + ycol] = lb16;
            } else {
                y1[m * Hn + ycol] = h;
            }
        }
        xcur = xnext;
    }

    mbar_wait(mb0, ph0);   // absorb final broadcast (4096 even -> mb0/ph0)
    cluster_sync_();
}

// ---------------------------------------------------------------------------
// 5) max over batch axis
// ---------------------------------------------------------------------------
__global__ void maxpool_kernel(const float* __restrict__ y1, float* __restrict__ out2)
{
    int idx = blockIdx.x * 256 + threadIdx.x;
    int s = idx >> 9, h = idx & 511;
    float mx = -3.402823466e38f;
    for (int b = 0; b < 128; b++) {
        float v = y1[((long)b * 128 + s) * Hn + h];
        mx = fmaxf(mx, v);
    }
    out2[idx] = mx;
}

// ---------------------------------------------------------------------------
extern "C" void kernel_launch(void* const* d_in, const int* in_sizes, int n_in,
                              void* d_out, int out_size)
{
    const int*   rt  = (const int*)d_in[0];
    const int*   re  = (const int*)d_in[1];
    const int*   rm  = (const int*)d_in[2];
    const float* h0  = (const float*)d_in[3];
    const float* c0  = (const float*)d_in[4];
    const float* Ert = (const float*)d_in[5];
    const float* Ere = (const float*)d_in[6];
    const float* Erm = (const float*)d_in[7];
    const float* Wih = (const float*)d_in[8];
    const float* Whh = (const float*)d_in[9];
    const float* bih = (const float*)d_in[10];
    const float* bhh = (const float*)d_in[11];

    float* out  = (float*)d_out;
    float* y1   = out;
    float* out2 = out + (long)Bn * Sn * Hn;

    void *p_x0, *p_x1, *p_a2, *p_w2, *p_b;
    cudaGetSymbolAddress(&p_x0, g_x0);
    cudaGetSymbolAddress(&p_x1, g_x1);
    cudaGetSymbolAddress(&p_a2, g_a2);
    cudaGetSymbolAddress(&p_w2, g_w2);
    cudaGetSymbolAddress(&p_b,  g_bias);
    float* gx0 = (float*)p_x0;
    float* gx1 = (float*)p_x1;
    __nv_bfloat16* a2 = (__nv_bfloat16*)p_a2;
    __nv_bfloat16* w2 = (__nv_bfloat16*)p_w2;
    float* bias = (float*)p_b;

    cudaFuncSetAttribute(gemm_mma_kernel,
                         cudaFuncAttributeMaxDynamicSharedMemorySize, GEMM_SMEM);

    // prep
    embed_split_kernel<<<NROW, 128>>>(rt, re, rm, Ert, Ere, Erm);
    w_split_kernel<<<dim3(2048, 2), 128>>>(Wih, bih, bhh);

    // layer 0
    gemm_mma_kernel<<<dim3(16, 128), 256, GEMM_SMEM>>>(a2, w2, bias, gx0);
    lstm_layer_kernel<<<64, 128>>>(Whh, gx0, y1, a2, h0, c0, 0);

    // layer 1
    gemm_mma_kernel<<<dim3(16, 128), 256, GEMM_SMEM>>>(
        a2, w2 + (long)2048 * KW, bias + 2048, gx1);
    lstm_layer_kernel<<<64, 128>>>(Whh, gx1, y1, a2, h0, c0, 1);

    maxpool_kernel<<<256, 256>>>(y1, out2);
}

// round 17
// speedup vs baseline: 3.2093x; 3.2093x over previous
#include <cuda_runtime.h>
#include <cuda_bf16.h>
#include <cstdint>

// ---------------------------------------------------------------------------
// EncoderBiLSTMMaxPool — consolidated best-proven configuration:
//   embed_split -> a2 [hi|lo] bf16            (R9+ proven)
//   w_split     -> w2 [hi|hi|lo] bf16         (R8+ proven)
//   gemm0 (mma.sync, 5-stage cp.async) -> gx0 (R13-profiled: 337us, tensor 50%)
//   lstm layer0 (R8 core, 256thr) -> writes h as split bf16 into a2
//   gemm1 -> gx1
//   lstm layer1 -> y1 (d_out)
//   maxpool over batch axis
// GEMM numerics: 3-term bf16 hi/lo split => rel_err ~4.7e-6 (proven R8-R15).
// ---------------------------------------------------------------------------

#define Bn   128
#define Sn   128
#define Hn   512
#define NROW 16384
#define GXN  2048
#define KA   1024
#define KW   1536

typedef unsigned long long ull;

__device__ __align__(16) float          g_x0[NROW * GXN];
__device__ __align__(16) float          g_x1[NROW * GXN];
__device__ __align__(16) __nv_bfloat16  g_a2[(long)NROW * KA];
__device__ __align__(16) __nv_bfloat16  g_w2[2L * GXN * KW];

// ---------------------------------------------------------------------------
// helpers
// ---------------------------------------------------------------------------
__device__ __forceinline__ unsigned smem_u32(const void* p) {
    return (unsigned)__cvta_generic_to_shared(p);
}
__device__ __forceinline__ unsigned mapa_cluster(unsigned addr, unsigned rank) {
    unsigned r;
    asm volatile("mapa.shared::cluster.u32 %0, %1, %2;" : "=r"(r) : "r"(addr), "r"(rank));
    return r;
}
__device__ __forceinline__ void cluster_sync_() {
    asm volatile("barrier.cluster.arrive.aligned;" ::: "memory");
    asm volatile("barrier.cluster.wait.aligned;" ::: "memory");
}
__device__ __forceinline__ void mbar_init(unsigned bar, unsigned cnt) {
    asm volatile("mbarrier.init.shared.b64 [%0], %1;" :: "r"(bar), "r"(cnt) : "memory");
}
__device__ __forceinline__ void mbar_arm(unsigned bar, unsigned tx) {
    asm volatile("mbarrier.arrive.expect_tx.shared::cta.b64 _, [%0], %1;"
                 :: "r"(bar), "r"(tx) : "memory");
}
__device__ __forceinline__ void mbar_wait(unsigned bar, unsigned parity) {
    asm volatile(
        "{\n\t.reg .pred P;\n"
        "LW%=:\n\t"
        "mbarrier.try_wait.parity.acquire.cta.shared::cta.b64 P, [%0], %1, 0x989680;\n\t"
        "@!P bra LW%=;\n\t}"
        :: "r"(bar), "r"(parity) : "memory");
}
__device__ __forceinline__ void st_async_f32(unsigned dst, float v, unsigned bar) {
    asm volatile("st.async.shared::cluster.mbarrier::complete_tx::bytes.b32 [%0], %1, [%2];"
                 :: "r"(dst), "r"(__float_as_uint(v)), "r"(bar) : "memory");
}
__device__ __forceinline__ float tanh_fast(float x) {
    float r;
    asm("tanh.approx.f32 %0, %1;" : "=f"(r) : "f"(x));
    return r;
}
__device__ __forceinline__ float sigmoid_fast(float x) {
    return fmaf(0.5f, tanh_fast(0.5f * x), 0.5f);
}
__device__ __forceinline__ void fma2(ull& acc, ull a, ull b) {
    asm("fma.rn.f32x2 %0, %1, %2, %0;" : "+l"(acc) : "l"(a), "l"(b));
}
__device__ __forceinline__ float sum2(ull a) {
    unsigned lo, hi;
    asm("mov.b64 {%0,%1}, %2;" : "=r"(lo), "=r"(hi) : "l"(a));
    return __uint_as_float(lo) + __uint_as_float(hi);
}

// --- mma.sync / ldmatrix / cp.async ---
__device__ __forceinline__ void cp16(unsigned dst, const void* src) {
    asm volatile("cp.async.cg.shared.global [%0], [%1], 16;" :: "r"(dst), "l"(src));
}
__device__ __forceinline__ void cp_commit() {
    asm volatile("cp.async.commit_group;" ::: "memory");
}
__device__ __forceinline__ void cp_wait3() {
    asm volatile("cp.async.wait_group 3;" ::: "memory");
}
__device__ __forceinline__ void ldsm4(unsigned* r, unsigned addr) {
    asm volatile("ldmatrix.sync.aligned.m8n8.x4.shared.b16 {%0,%1,%2,%3}, [%4];"
                 : "=r"(r[0]), "=r"(r[1]), "=r"(r[2]), "=r"(r[3]) : "r"(addr));
}
__device__ __forceinline__ void mma16816(float* c, const unsigned* a,
                                         unsigned b0, unsigned b1) {
    asm volatile(
        "mma.sync.aligned.m16n8k16.row.col.f32.bf16.bf16.f32 "
        "{%0,%1,%2,%3}, {%4,%5,%6,%7}, {%8,%9}, {%0,%1,%2,%3};"
        : "+f"(c[0]), "+f"(c[1]), "+f"(c[2]), "+f"(c[3])
        : "r"(a[0]), "r"(a[1]), "r"(a[2]), "r"(a[3]), "r"(b0), "r"(b1));
}

__device__ __forceinline__ uint2 pack4bf16(float a, float b, float c, float d) {
    __nv_bfloat162 p0 = __floats2bfloat162_rn(a, b);
    __nv_bfloat162 p1 = __floats2bfloat162_rn(c, d);
    uint2 r;
    r.x = *(unsigned*)&p0;
    r.y = *(unsigned*)&p1;
    return r;
}
__device__ __forceinline__ void split4(const float* v, float* hi, float* lo) {
#pragma unroll
    for (int j = 0; j < 4; j++) {
        __nv_bfloat16 h = __float2bfloat16_rn(v[j]);
        hi[j] = __bfloat162float(h);
        lo[j] = v[j] - hi[j];
    }
}

// ---------------------------------------------------------------------------
// 1) embedding sum + split -> a2 rows [hi | lo]
// ---------------------------------------------------------------------------
__global__ void embed_split_kernel(const int* __restrict__ rt, const int* __restrict__ re,
                                   const int* __restrict__ rm,
                                   const float* __restrict__ Ert, const float* __restrict__ Ere,
                                   const float* __restrict__ Erm)
{
    int row = blockIdx.x;
    int t   = threadIdx.x;
    long irt = rt[row], ire = re[row], irm = rm[row];
    float4 va = ((const float4*)(Ert + irt * (long)Hn))[t];
    float4 vb = ((const float4*)(Ere + ire * (long)Hn))[t];
    float4 vc = ((const float4*)(Erm + irm * (long)Hn))[t];
    float v[4] = { va.x + vb.x + vc.x, va.y + vb.y + vc.y,
                   va.z + vb.z + vc.z, va.w + vb.w + vc.w };
    float hi[4], lo[4];
    split4(v, hi, lo);
    __nv_bfloat16* ro = g_a2 + (long)row * KA + 4 * t;
    *(uint2*)(ro)       = pack4bf16(hi[0], hi[1], hi[2], hi[3]);
    *(uint2*)(ro + 512) = pack4bf16(lo[0], lo[1], lo[2], lo[3]);
}

// split Wih -> w2 rows [hi | hi | lo]
__global__ void w_split_kernel(const float* __restrict__ Wih)
{
    int n = blockIdx.x;
    int l = blockIdx.y;
    int t = threadIdx.x;
    float4 vv = *(const float4*)(Wih + ((long)l * 2048 + n) * 512 + 4 * t);
    float v[4] = { vv.x, vv.y, vv.z, vv.w };
    float hi[4], lo[4];
    split4(v, hi, lo);
    __nv_bfloat16* ro = g_w2 + ((long)l * 2048 + n) * KW + 4 * t;
    uint2 ph = pack4bf16(hi[0], hi[1], hi[2], hi[3]);
    *(uint2*)(ro)        = ph;
    *(uint2*)(ro + 512)  = ph;
    *(uint2*)(ro + 1024) = pack4bf16(lo[0], lo[1], lo[2], lo[3]);
}

// ---------------------------------------------------------------------------
// 2) mma.sync bf16 GEMM over K=1536, A k-map (k>=1024 re-reads hi block).
//    Block 128x128, warps 4x2, warp tile 32x64, BK=32, 5-stage cp.async.
//    (Profiled R13-R15: 337us, tensor pipe 50.5%.)
// ---------------------------------------------------------------------------
#define ROWB       80
#define A_BYTES    (128 * ROWB)
#define STAGE_B    (2 * A_BYTES)
#define NSTAGE     5
#define GEMM_SMEM  (NSTAGE * STAGE_B)     // 102400
#define NKT        (KW / 32)              // 48

__global__ __launch_bounds__(256, 2) void gemm_mma_kernel(
    const __nv_bfloat16* __restrict__ A2, const __nv_bfloat16* __restrict__ W2,
    const float* __restrict__ bih, const float* __restrict__ bhh,
    float* __restrict__ C)
{
    extern __shared__ __align__(16) char dyn[];
    __shared__ float bias_s[128];

    const int tid  = threadIdx.x;
    const int wid  = tid >> 5;
    const int lane = tid & 31;
    const int wm   = wid & 3;
    const int wn   = wid >> 2;
    const int bm = blockIdx.y * 128;
    const int bn = blockIdx.x * 128;

    if (tid < 128) bias_s[tid] = bih[bn + tid] + bhh[bn + tid];

    const unsigned sbase = smem_u32(dyn);
    const int g  = lane >> 3;
    const int rr = lane & 7;
    const unsigned a_lane = (unsigned)((wm * 32 + (g & 1) * 8 + rr) * ROWB + (g >> 1) * 16);
    const unsigned b_lane = (unsigned)((wn * 64 + (g >> 1) * 8 + rr) * ROWB + (g & 1) * 16);

    float acc[2][8][4];
#pragma unroll
    for (int i = 0; i < 2; i++)
#pragma unroll
        for (int j = 0; j < 8; j++)
#pragma unroll
            for (int q = 0; q < 4; q++) acc[i][j][q] = 0.f;

    auto issue_loads = [&](int kt) {
        unsigned stage = sbase + (unsigned)(kt % NSTAGE) * STAGE_B;
        long k0 = (long)kt * 32;
        long ak = (k0 < 1024) ? k0 : (k0 - 1024);
#pragma unroll
        for (int i = 0; i < 4; i++) {
            int c = tid + i * 256;
            if (c < 512) {
                int row = c >> 2, ch = c & 3;
                cp16(stage + row * ROWB + ch * 16,
                     A2 + (long)(bm + row) * KA + ak + ch * 8);
            } else {
                int c2 = c - 512;
                int row = c2 >> 2, ch = c2 & 3;
                cp16(stage + A_BYTES + row * ROWB + ch * 16,
                     W2 + (long)(bn + row) * KW + k0 + ch * 8);
            }
        }
    };

    issue_loads(0); cp_commit();
    issue_loads(1); cp_commit();
    issue_loads(2); cp_commit();
    issue_loads(3); cp_commit();

    for (int kt = 0; kt < NKT; kt++) {
        cp_wait3();
        __syncthreads();
        unsigned stage  = sbase + (unsigned)(kt % NSTAGE) * STAGE_B;
        unsigned stageB = stage + A_BYTES;
#pragma unroll
        for (int kk = 0; kk < 2; kk++) {
            unsigned afrag[2][4];
#pragma unroll
            for (int mi = 0; mi < 2; mi++)
                ldsm4(afrag[mi], stage + a_lane + mi * 16 * ROWB + kk * 32);
            unsigned bfrag[4][4];
#pragma unroll
            for (int p = 0; p < 4; p++)
                ldsm4(bfrag[p], stageB + b_lane + p * 16 * ROWB + kk * 32);
#pragma unroll
            for (int mi = 0; mi < 2; mi++)
#pragma unroll
                for (int p = 0; p < 4; p++) {
                    mma16816(acc[mi][2 * p],     afrag[mi], bfrag[p][0], bfrag[p][1]);
                    mma16816(acc[mi][2 * p + 1], afrag[mi], bfrag[p][2], bfrag[p][3]);
                }
        }
        __syncthreads();
        if (kt + 4 < NKT) issue_loads(kt + 4);
        cp_commit();
    }

    const int trow = lane >> 2;
    const int tcol = (lane & 3) * 2;
#pragma unroll
    for (int mi = 0; mi < 2; mi++) {
        int m0 = bm + wm * 32 + mi * 16 + trow;
#pragma unroll
        for (int nj = 0; nj < 8; nj++) {
            int cl = wn * 64 + nj * 8 + tcol;
            int n0 = bn + cl;
            float b0 = bias_s[cl], b1 = bias_s[cl + 1];
            *(float2*)(C + (long)m0 * GXN + n0) =
                make_float2(acc[mi][nj][0] + b0, acc[mi][nj][1] + b1);
            *(float2*)(C + (long)(m0 + 8) * GXN + n0) =
                make_float2(acc[mi][nj][2] + b0, acc[mi][nj][3] + b1);
        }
    }
}

// ---------------------------------------------------------------------------
// 3) LSTM recurrence — R8 core verbatim (256 thr, half-split dot, smem
//    combine). layer==0 writes h as split bf16 into a2; layer==1 writes y1.
// ---------------------------------------------------------------------------
__global__ void __cluster_dims__(8, 1, 1) __launch_bounds__(256, 1)
lstm_layer_kernel(const float* __restrict__ Whh, const float* __restrict__ gx,
                  float* __restrict__ y1, __nv_bfloat16* __restrict__ a2,
                  const float* __restrict__ h0, const float* __restrict__ c0,
                  int layer)
{
    __shared__ __align__(16) float h_buf[2][256];
    __shared__ float partial[256];
    __shared__ __align__(8) ull mbar[2];

    unsigned rank;
    asm("mov.u32 %0, %%cluster_ctarank;" : "=r"(rank));
    const int cluster_id = blockIdx.x >> 3;
    const int group = cluster_id & 3;
    const int dir   = cluster_id >> 2;
    const int tid = threadIdx.x;
    const int row_local = tid & 127;
    const int half = tid >> 7;
    const int gate = row_local >> 5;
    const int ul   = row_local & 31;
    const int unit = (int)rank * 32 + ul;
    const int grow = gate * 256 + unit;

    ulonglong2 w[32];
    const ulonglong2* wsrc = (const ulonglong2*)(Whh
        + ((long)(layer * 2 + dir) * 1024 + grow) * 256 + half * 128);
#pragma unroll
    for (int j = 0; j < 32; j++) w[j] = wsrc[j];

    const int sidx = (layer * 2 + dir) * 256;
    h_buf[0][tid] = (group == 0) ? h0[sidx + tid] : 0.f;
    float creg = 0.f;
    if (tid < 32) creg = (group == 0) ? c0[sidx + (int)rank * 32 + tid] : 0.f;

    unsigned mb0 = smem_u32(&mbar[0]);
    unsigned mb1 = smem_u32(&mbar[1]);
    if (tid == 0) {
        mbar_init(mb0, 1);
        mbar_init(mb1, 1);
        mbar_arm(mb1, 1024);   // consumed at q=1
        mbar_arm(mb0, 1024);   // consumed at q=2
    }
    __syncthreads();
    cluster_sync_();

    const int xcol = dir * 1024 + grow;
    const int ycol = dir * 256 + unit;
    const long mbase = (long)group * 32 * 128;
    unsigned ph0 = 0, ph1 = 0;

    auto midx = [&](int q) -> long {
        int t = q & 127;
        if (dir) t = 127 - t;
        return mbase + (q & ~127) + t;
    };

    float xcur = (tid < 128) ? __ldg(gx + midx(0) * GXN + xcol) : 0.f;

    for (int q = 0; q < 4096; q++) {
        const int p = q & 1;

        float xnext = 0.f;
        if (tid < 128 && q + 1 < 4096)
            xnext = __ldg(gx + midx(q + 1) * GXN + xcol);

        if (q > 0) {
            if (p) { mbar_wait(mb1, ph1); ph1 ^= 1; }
            else   { mbar_wait(mb0, ph0); ph0 ^= 1; }
            if (tid == 1) mbar_arm(p ? mb1 : mb0, 1024);   // re-arm for q+2
        }

        const ulonglong2* hb = ((const ulonglong2*)h_buf[p]) + half * 32;
        ull acc0 = 0, acc1 = 0;
#pragma unroll
        for (int j = 0; j < 32; j++) {
            ulonglong2 hv = hb[j];
            fma2(acc0, hv.x, w[j].x);
            fma2(acc1, hv.y, w[j].y);
        }
        float s = sum2(acc0) + sum2(acc1);
        partial[tid] = (tid < 128) ? (s + xcur) : s;
        __syncthreads();

        if (tid < 32) {
            float iv = partial[tid]      + partial[tid + 128];
            float fv = partial[tid + 32] + partial[tid + 160];
            float gv = partial[tid + 64] + partial[tid + 192];
            float ov = partial[tid + 96] + partial[tid + 224];
            float ig = sigmoid_fast(iv);
            float fg = sigmoid_fast(fv);
            float og = sigmoid_fast(ov);
            float gg = tanh_fast(gv);
            creg = fmaf(fg, creg, ig * gg);
            float h = og * tanh_fast(creg);

            // broadcast first (latency-critical), then write outputs
            const int pn = p ^ 1;
            unsigned ldst = smem_u32(&h_buf[pn][unit]);
            unsigned lbar = pn ? mb1 : mb0;
#pragma unroll
            for (unsigned r = 0; r < 8; r++)
                st_async_f32(mapa_cluster(ldst, r), h, mapa_cluster(lbar, r));

            const long m = midx(q);
            if (layer == 0) {
                __nv_bfloat16 hb16 = __float2bfloat16_rn(h);
                float hf = __bfloat162float(hb16);
                __nv_bfloat16 lb16 = __float2bfloat16_rn(h - hf);
                a2[m * KA + ycol]       = hb16;
                a2[m * KA + 512 + ycol] = lb16;
            } else {
                y1[m * Hn + ycol] = h;
            }
        }
        xcur = xnext;
    }

    mbar_wait(mb0, ph0);   // absorb final broadcast (4096 even -> mb0/ph0)
    cluster_sync_();
}

// ---------------------------------------------------------------------------
// 5) max over batch axis
// ---------------------------------------------------------------------------
__global__ void maxpool_kernel(const float* __restrict__ y1, float* __restrict__ out2)
{
    int idx = blockIdx.x * 256 + threadIdx.x;    // 0..65535
    int s = idx >> 9, h = idx & 511;
    float mx = -3.402823466e38f;
    for (int b = 0; b < 128; b++) {
        float v = y1[((long)b * 128 + s) * Hn + h];
        mx = fmaxf(mx, v);
    }
    out2[idx] = mx;
}

// ---------------------------------------------------------------------------
extern "C" void kernel_launch(void* const* d_in, const int* in_sizes, int n_in,
                              void* d_out, int out_size)
{
    const int*   rt  = (const int*)d_in[0];
    const int*   re  = (const int*)d_in[1];
    const int*   rm  = (const int*)d_in[2];
    const float* h0  = (const float*)d_in[3];
    const float* c0  = (const float*)d_in[4];
    const float* Ert = (const float*)d_in[5];
    const float* Ere = (const float*)d_in[6];
    const float* Erm = (const float*)d_in[7];
    const float* Wih = (const float*)d_in[8];
    const float* Whh = (const float*)d_in[9];
    const float* bih = (const float*)d_in[10];
    const float* bhh = (const float*)d_in[11];

    float* out  = (float*)d_out;
    float* y1   = out;                       // bilstm_outs (128,128,512)
    float* out2 = out + (long)Bn * Sn * Hn;  // output (128,512)

    void *p_x0, *p_x1, *p_a2, *p_w2;
    cudaGetSymbolAddress(&p_x0, g_x0);
    cudaGetSymbolAddress(&p_x1, g_x1);
    cudaGetSymbolAddress(&p_a2, g_a2);
    cudaGetSymbolAddress(&p_w2, g_w2);
    float* gx0 = (float*)p_x0;
    float* gx1 = (float*)p_x1;
    __nv_bfloat16* a2 = (__nv_bfloat16*)p_a2;
    __nv_bfloat16* w2 = (__nv_bfloat16*)p_w2;

    cudaFuncSetAttribute(gemm_mma_kernel,
                         cudaFuncAttributeMaxDynamicSharedMemorySize, GEMM_SMEM);

    // prep
    embed_split_kernel<<<NROW, 128>>>(rt, re, rm, Ert, Ere, Erm);
    w_split_kernel<<<dim3(2048, 2), 128>>>(Wih);

    // layer 0
    gemm_mma_kernel<<<dim3(16, 128), 256, GEMM_SMEM>>>(a2, w2, bih, bhh, gx0);
    lstm_layer_kernel<<<64, 256>>>(Whh, gx0, y1, a2, h0, c0, 0);

    // layer 1 (a2 now holds split layer-0 outputs)
    gemm_mma_kernel<<<dim3(16, 128), 256, GEMM_SMEM>>>(
        a2, w2 + (long)2048 * KW, bih + 2048, bhh + 2048, gx1);
    lstm_layer_kernel<<<64, 256>>>(Whh, gx1, y1, a2, h0, c0, 1);

    maxpool_kernel<<<256, 256>>>(y1, out2);
}